// round 1
// baseline (speedup 1.0000x reference)
#include <cuda_runtime.h>
#include <math.h>

// Problem shape (fixed by the dataset): B=2, N=512, R=4
#define Bb 2
#define Nn 512
#define Rr 4
#define BR (Bb * Rr)

// Scratch: masked sigmoid probabilities, laid out per (b,r) matrix [BR][N][N]
__device__ float  g_rel[BR * Nn * Nn];
__device__ double g_lin;
__device__ double g_abs;

// ---------------------------------------------------------------------------
// Zero the accumulators (must run every launch: graph replays)
// ---------------------------------------------------------------------------
__global__ void zero_kernel() {
    g_lin = 0.0;
    g_abs = 0.0;
}

// ---------------------------------------------------------------------------
// prep: rel[(b*R+r)][a][c] = sigmoid(logits[b][a][c][r]) * m[b][a] * m[b][c]
// One thread per (b,a,c); reads float4 (the R=4 innermost dim), scatters to
// the 4 matrices. Consecutive threads -> consecutive c -> coalesced stores.
// ---------------------------------------------------------------------------
__global__ void prep_kernel(const float* __restrict__ logits,
                            const int*   __restrict__ masks) {
    int idx = blockIdx.x * blockDim.x + threadIdx.x;   // over B*N*N
    if (idx >= Bb * Nn * Nn) return;
    int b   = idx / (Nn * Nn);
    int rem = idx - b * (Nn * Nn);
    int a   = rem / Nn;
    int c   = rem - a * Nn;

    float4 lg = reinterpret_cast<const float4*>(logits)[idx];
    float mm = (masks[b * Nn + a] > 0 && masks[b * Nn + c] > 0) ? 1.0f : 0.0f;

    float p0 = mm / (1.0f + __expf(-lg.x));
    float p1 = mm / (1.0f + __expf(-lg.y));
    float p2 = mm / (1.0f + __expf(-lg.z));
    float p3 = mm / (1.0f + __expf(-lg.w));

    int base = a * Nn + c;
    g_rel[((b * Rr + 0) * Nn * Nn) + base] = p0;
    g_rel[((b * Rr + 1) * Nn * Nn) + base] = p1;
    g_rel[((b * Rr + 2) * Nn * Nn) + base] = p2;
    g_rel[((b * Rr + 3) * Nn * Nn) + base] = p3;
}

// ---------------------------------------------------------------------------
// Linear term, exact O(N^2):
//   S_lin = sum_{br} sum_c [ N*s_c - s_c^2 ],   s_c = sum_a M[a][c]
// One thread per (br, c). Column reads are coalesced across threads.
// ---------------------------------------------------------------------------
__global__ void colsum_kernel() {
    int br = blockIdx.x >> 2;                      // 0..7
    int c  = ((blockIdx.x & 3) << 7) + threadIdx.x; // 0..511 (128 thr/blk)
    const float* __restrict__ M = g_rel + br * Nn * Nn;
    float s = 0.0f;
    #pragma unroll 8
    for (int a = 0; a < Nn; ++a) s += M[a * Nn + c];
    double v = (double)s * (double)(Nn - (double)s);
    atomicAdd(&g_lin, v);
}

// ---------------------------------------------------------------------------
// Cube kernel: S_abs = sum_{br,a,b,c} | M[a][b] - M[a][c]*M[b][c] |
// Block = one (br, 64x64 (a,b) tile). Thread = 4x4 register tile, holds -M
// so inner op is t = fma(pa, pb, mneg) = pa*pb - M  and  acc += |t|
// (FADD abs-modifier is free in SASS). c staged through shared in 64-chunks,
// [row][c] layout with pad 65 -> conflict-free/broadcast column reads.
// Grid 8x8x8 = 512 blocks -> single wave at >=4 blocks/SM.
// ---------------------------------------------------------------------------
__global__ void __launch_bounds__(256) cube_kernel() {
    __shared__ float tA[64][65];
    __shared__ float tB[64][65];
    __shared__ float wsum[8];

    const float* __restrict__ M = g_rel + blockIdx.z * (Nn * Nn);
    const int a0 = blockIdx.y * 64;
    const int b0 = blockIdx.x * 64;
    const int tid = threadIdx.x;
    const int tx = tid & 15;
    const int ty = tid >> 4;
    const int ay = ty * 4;
    const int bx = tx * 4;

    // Load this thread's 4x4 of M, negated.
    float mn[4][4];
    #pragma unroll
    for (int i = 0; i < 4; ++i) {
        float4 v = *reinterpret_cast<const float4*>(&M[(a0 + ay + i) * Nn + b0 + bx]);
        mn[i][0] = -v.x; mn[i][1] = -v.y; mn[i][2] = -v.z; mn[i][3] = -v.w;
    }

    float acc[4] = {0.f, 0.f, 0.f, 0.f};

    const int lr = tid >> 2;           // staging row 0..63
    const int lc = (tid & 3) * 16;     // staging col segment

    for (int c0 = 0; c0 < Nn; c0 += 64) {
        __syncthreads();
        #pragma unroll
        for (int k = 0; k < 16; k += 4) {
            float4 va = *reinterpret_cast<const float4*>(&M[(a0 + lr) * Nn + c0 + lc + k]);
            tA[lr][lc + k + 0] = va.x; tA[lr][lc + k + 1] = va.y;
            tA[lr][lc + k + 2] = va.z; tA[lr][lc + k + 3] = va.w;
            float4 vb = *reinterpret_cast<const float4*>(&M[(b0 + lr) * Nn + c0 + lc + k]);
            tB[lr][lc + k + 0] = vb.x; tB[lr][lc + k + 1] = vb.y;
            tB[lr][lc + k + 2] = vb.z; tB[lr][lc + k + 3] = vb.w;
        }
        __syncthreads();

        #pragma unroll 4
        for (int c = 0; c < 64; ++c) {
            float pa0 = tA[ay + 0][c], pa1 = tA[ay + 1][c];
            float pa2 = tA[ay + 2][c], pa3 = tA[ay + 3][c];
            float pb0 = tB[bx + 0][c], pb1 = tB[bx + 1][c];
            float pb2 = tB[bx + 2][c], pb3 = tB[bx + 3][c];

            float s0 = (fabsf(fmaf(pa0, pb0, mn[0][0])) + fabsf(fmaf(pa0, pb1, mn[0][1])))
                     + (fabsf(fmaf(pa0, pb2, mn[0][2])) + fabsf(fmaf(pa0, pb3, mn[0][3])));
            float s1 = (fabsf(fmaf(pa1, pb0, mn[1][0])) + fabsf(fmaf(pa1, pb1, mn[1][1])))
                     + (fabsf(fmaf(pa1, pb2, mn[1][2])) + fabsf(fmaf(pa1, pb3, mn[1][3])));
            float s2 = (fabsf(fmaf(pa2, pb0, mn[2][0])) + fabsf(fmaf(pa2, pb1, mn[2][1])))
                     + (fabsf(fmaf(pa2, pb2, mn[2][2])) + fabsf(fmaf(pa2, pb3, mn[2][3])));
            float s3 = (fabsf(fmaf(pa3, pb0, mn[3][0])) + fabsf(fmaf(pa3, pb1, mn[3][1])))
                     + (fabsf(fmaf(pa3, pb2, mn[3][2])) + fabsf(fmaf(pa3, pb3, mn[3][3])));

            acc[c & 3] += (s0 + s1) + (s2 + s3);
        }
    }

    float tsum = (acc[0] + acc[1]) + (acc[2] + acc[3]);
    #pragma unroll
    for (int o = 16; o > 0; o >>= 1)
        tsum += __shfl_xor_sync(0xffffffffu, tsum, o);
    if ((tid & 31) == 0) wsum[tid >> 5] = tsum;
    __syncthreads();
    if (tid == 0) {
        float bsum = 0.f;
        #pragma unroll
        for (int w = 0; w < 8; ++w) bsum += wsum[w];
        atomicAdd(&g_abs, (double)bsum);
    }
}

// ---------------------------------------------------------------------------
// Finalize:  out = WEIGHT * 0.5*(S_lin + S_abs) / (R*B)
// ---------------------------------------------------------------------------
__global__ void fin_kernel(float* __restrict__ out, int n) {
    double v = 0.5 * (g_lin + g_abs) / (double)(Bb * Rr);
    for (int i = threadIdx.x; i < n; i += blockDim.x) out[i] = (float)v;
}

extern "C" void kernel_launch(void* const* d_in, const int* in_sizes, int n_in,
                              void* d_out, int out_size) {
    const float* logits = (const float*)d_in[0];   // [B, N, N, R] f32
    const int*   masks  = (const int*)d_in[1];     // [B, N] i32

    zero_kernel<<<1, 1>>>();
    prep_kernel<<<(Bb * Nn * Nn + 255) / 256, 256>>>(logits, masks);
    colsum_kernel<<<BR * 4, 128>>>();
    dim3 grid(8, 8, 8);   // (b-tile, a-tile, br)
    cube_kernel<<<grid, 256>>>();
    fin_kernel<<<1, 32>>>((float*)d_out, out_size);
}